// round 3
// baseline (speedup 1.0000x reference)
#include <cuda_runtime.h>
#include <cuda_bf16.h>
#include <math.h>

// ---------------------------------------------------------------------------
// UNet forward, fp32 direct implementation.
// Inputs (metadata order):
//  0 x(4,1,256,256) 1 w(4,32,4,4) 2 d1w(32,32,4,4) 3 d1b(32)
//  4 w2a(128,32,3,3) 5 b2a 6 w2b(128,128,3,3) 7 b2b
//  8 w3a(256,128,3,3) 9 b3a 10 w3b(256,256,3,3) 11 b3b
// 12 w4a(512,256,3,3) 13 b4a 14 w4b(512,512,3,3) 15 b4b
// 16 g4(512) 17 be4(512)
// 18 u3a(256,768,3,3) 19 ub3a 20 u3b(256,256,3,3) 21 ub3b
// 22 u2a(128,384,3,3) 23 ub2a 24 u2b(128,128,3,3) 25 ub2b
// 26 u1a(32,160,3,3) 27 ub1a 28 u1b(32,32,3,3) 29 ub1b
// 30 wl(1,32,1,1) 31 bl(1)
// ---------------------------------------------------------------------------

#define BN_EPS 1e-5f

// ------------------------- scratch buffers ---------------------------------
constexpr size_t SZ_T0   = 4ul*32*255*255;   // dyn conv out
constexpr size_t SZ_C1   = 4ul*32*256*256;
constexpr size_t SZ_P1   = 4ul*32*128*128;
constexpr size_t SZ_A2   = 4ul*128*128*128;
constexpr size_t SZ_C2   = 4ul*128*128*128;
constexpr size_t SZ_P2   = 4ul*128*64*64;
constexpr size_t SZ_A3   = 4ul*256*64*64;
constexpr size_t SZ_C3   = 4ul*256*64*64;
constexpr size_t SZ_P3   = 4ul*256*32*32;
constexpr size_t SZ_A4   = 4ul*512*32*32;
constexpr size_t SZ_H4   = 4ul*512*32*32;
constexpr size_t SZ_CAT3 = 4ul*768*64*64;
constexpr size_t SZ_A5   = 4ul*256*64*64;
constexpr size_t SZ_U3   = 4ul*256*64*64;
constexpr size_t SZ_CAT2 = 4ul*384*128*128;
constexpr size_t SZ_A6   = 4ul*128*128*128;
constexpr size_t SZ_U2   = 4ul*128*128*128;
constexpr size_t SZ_CAT1 = 4ul*160*256*256;
constexpr size_t SZ_A7   = 4ul*32*256*256;
constexpr size_t SZ_U1   = 4ul*32*256*256;

constexpr size_t OFF_T0   = 0;
constexpr size_t OFF_C1   = OFF_T0   + SZ_T0;
constexpr size_t OFF_P1   = OFF_C1   + SZ_C1;
constexpr size_t OFF_A2   = OFF_P1   + SZ_P1;
constexpr size_t OFF_C2   = OFF_A2   + SZ_A2;
constexpr size_t OFF_P2   = OFF_C2   + SZ_C2;
constexpr size_t OFF_A3   = OFF_P2   + SZ_P2;
constexpr size_t OFF_C3   = OFF_A3   + SZ_A3;
constexpr size_t OFF_P3   = OFF_C3   + SZ_C3;
constexpr size_t OFF_A4   = OFF_P3   + SZ_P3;
constexpr size_t OFF_H4   = OFF_A4   + SZ_A4;
constexpr size_t OFF_CAT3 = OFF_H4   + SZ_H4;
constexpr size_t OFF_A5   = OFF_CAT3 + SZ_CAT3;
constexpr size_t OFF_U3   = OFF_A5   + SZ_A5;
constexpr size_t OFF_CAT2 = OFF_U3   + SZ_U3;
constexpr size_t OFF_A6   = OFF_CAT2 + SZ_CAT2;
constexpr size_t OFF_U2   = OFF_A6   + SZ_A6;
constexpr size_t OFF_CAT1 = OFF_U2   + SZ_U2;
constexpr size_t OFF_A7   = OFF_CAT1 + SZ_CAT1;
constexpr size_t OFF_U1   = OFF_A7   + SZ_A7;
constexpr size_t TOTAL_F  = OFF_U1   + SZ_U1;

__device__ float g_buf[TOTAL_F];

// ------------------------- helpers -----------------------------------------
__device__ __forceinline__ float mishf(float x) {
    // x * tanh(softplus(x)); stable softplus
    float sp = (x > 20.f) ? x : log1pf(expf(x));
    return x * tanhf(sp);
}

// ------------------------- dyn conv + mish ----------------------------------
// x (4,1,256,256), w (4,32,4,4), pad=1 -> out (4,32,255,255)
__global__ void dynconv_mish_kernel(const float* __restrict__ x,
                                    const float* __restrict__ w,
                                    float* __restrict__ out) {
    const int HO = 255, WO = 255;
    int idx = blockIdx.x * blockDim.x + threadIdx.x;
    int total = 4 * 32 * HO * WO;
    if (idx >= total) return;
    int ox = idx % WO; int t = idx / WO;
    int oy = t % HO;  t /= HO;
    int co = t & 31;  int b = t >> 5;
    const float* xb = x + (size_t)b * 256 * 256;
    const float* wb = w + ((size_t)(b * 32 + co) << 4);
    float acc = 0.f;
#pragma unroll
    for (int ky = 0; ky < 4; ky++) {
        int iy = oy - 1 + ky;
        if (iy < 0 || iy >= 256) continue;
#pragma unroll
        for (int kx = 0; kx < 4; kx++) {
            int ix = ox - 1 + kx;
            if (ix < 0 || ix >= 256) continue;
            acc = fmaf(xb[iy * 256 + ix], wb[ky * 4 + kx], acc);
        }
    }
    out[idx] = mishf(acc);
}

// ------------------------- tiled direct conv --------------------------------
// Output tile 32x16, 128 threads, 4 pixels/thread (x), 8 out-channels/block.
// Requires: Wo % 32 == 0, Ho % 16 == 0, Co % 8 == 0, Ci % 4 == 0.
constexpr int TW = 32, TH = 16, PX = 4, GC = 8, CC = 4, NT = 128;

template<int K, bool MISH>
__global__ __launch_bounds__(NT) void conv_tiled(
    const float* __restrict__ in, const float* __restrict__ wgt,
    const float* __restrict__ bias, float* __restrict__ out,
    int Ci, int Hi, int Wi, int Co, int Ho, int Wo, int pad)
{
    constexpr int SH = TH + K - 1;       // <= 19
    constexpr int SW = TW + K - 1;       // <= 35
    constexpr int SWP = 37;              // conflict-free row stride
    __shared__ float s_tile[CC][SH][SWP];
    __shared__ float s_w[CC][GC][K * K];

    const int tid = threadIdx.x;
    const int tx = tid & 7;              // 0..7 -> 4-pixel groups
    const int ty = tid >> 3;             // 0..15
    const int ox0 = blockIdx.x * TW;
    const int oy0 = blockIdx.y * TH;
    const int ngrp = Co / GC;
    const int cogrp = blockIdx.z % ngrp;
    const int b = blockIdx.z / ngrp;
    const int co0 = cogrp * GC;

    float acc[GC][PX];
#pragma unroll
    for (int g = 0; g < GC; g++)
#pragma unroll
        for (int p = 0; p < PX; p++) acc[g][p] = 0.f;

    const float* inb = in + (size_t)b * Ci * Hi * Wi;

    for (int ci0 = 0; ci0 < Ci; ci0 += CC) {
        __syncthreads();
        // input tiles
        for (int idx = tid; idx < CC * SH * SW; idx += NT) {
            int cc = idx / (SH * SW);
            int r = idx - cc * (SH * SW);
            int sy = r / SW;
            int sx = r - sy * SW;
            int iy = oy0 - pad + sy;
            int ix = ox0 - pad + sx;
            float v = 0.f;
            if (iy >= 0 && iy < Hi && ix >= 0 && ix < Wi)
                v = inb[((size_t)(ci0 + cc) * Hi + iy) * Wi + ix];
            s_tile[cc][sy][sx] = v;
        }
        // weights
        for (int idx = tid; idx < CC * GC * K * K; idx += NT) {
            int cc = idx / (GC * K * K);
            int r = idx - cc * (GC * K * K);
            int g = r / (K * K);
            int kk = r - g * (K * K);
            s_w[cc][g][kk] = wgt[((size_t)(co0 + g) * Ci + ci0 + cc) * (K * K) + kk];
        }
        __syncthreads();

#pragma unroll
        for (int cc = 0; cc < CC; cc++) {
            float tv[K][PX + K - 1];
#pragma unroll
            for (int ky = 0; ky < K; ky++)
#pragma unroll
                for (int j = 0; j < PX + K - 1; j++)
                    tv[ky][j] = s_tile[cc][ty + ky][tx * PX + j];
#pragma unroll
            for (int g = 0; g < GC; g++) {
#pragma unroll
                for (int ky = 0; ky < K; ky++)
#pragma unroll
                    for (int kx = 0; kx < K; kx++) {
                        float wv = s_w[cc][g][ky * K + kx];
#pragma unroll
                        for (int p = 0; p < PX; p++)
                            acc[g][p] = fmaf(tv[ky][kx + p], wv, acc[g][p]);
                    }
            }
        }
    }

    const int oy = oy0 + ty;
    const int ox = ox0 + tx * PX;
#pragma unroll
    for (int g = 0; g < GC; g++) {
        float bv = bias[co0 + g];
        size_t base = (((size_t)b * Co + co0 + g) * Ho + oy) * Wo + ox;
#pragma unroll
        for (int p = 0; p < PX; p++) {
            float v = acc[g][p] + bv;
            if (MISH) v = mishf(v);
            out[base + p] = v;
        }
    }
}

// ------------------------- maxpool 2x2 --------------------------------------
__global__ void maxpool_kernel(const float* __restrict__ in, float* __restrict__ out,
                               int BC, int Hi, int Wi) {
    int Ho = Hi >> 1, Wo = Wi >> 1;
    int idx = blockIdx.x * blockDim.x + threadIdx.x;
    int total = BC * Ho * Wo;
    if (idx >= total) return;
    int ox = idx % Wo; int t = idx / Wo;
    int oy = t % Ho; int bc = t / Ho;
    const float* p = in + ((size_t)bc * Hi + 2 * oy) * Wi + 2 * ox;
    float m = fmaxf(fmaxf(p[0], p[1]), fmaxf(p[Wi], p[Wi + 1]));
    out[idx] = m;
}

// ------------------------- bilinear up x2 (align_corners) -------------------
__global__ void up2_kernel(const float* __restrict__ in, float* __restrict__ out,
                           int B, int C, int H, int W, int Ctot, int coff, float scale) {
    int Ho = 2 * H, Wo = 2 * W;
    int idx = blockIdx.x * blockDim.x + threadIdx.x;
    int total = B * C * Ho * Wo;
    if (idx >= total) return;
    int ox = idx % Wo; int t = idx / Wo;
    int oy = t % Ho; t /= Ho;
    int c = t % C; int b = t / C;
    float sy = oy * scale;
    float sx = ox * scale;
    int y0 = (int)floorf(sy); int y1 = min(y0 + 1, H - 1); float fy = sy - y0;
    int x0 = (int)floorf(sx); int x1 = min(x0 + 1, W - 1); float fx = sx - x0;
    const float* p = in + ((size_t)b * C + c) * H * W;
    float v00 = p[y0 * W + x0], v01 = p[y0 * W + x1];
    float v10 = p[y1 * W + x0], v11 = p[y1 * W + x1];
    float a0 = v00 * (1.f - fy) + v10 * fy;
    float a1 = v01 * (1.f - fy) + v11 * fy;
    out[((size_t)b * Ctot + coff + c) * Ho * Wo + (size_t)oy * Wo + ox] =
        a0 * (1.f - fx) + a1 * fx;
}

// ------------------------- skip copy into concat ----------------------------
__global__ void catcopy_kernel(const float* __restrict__ src, float* __restrict__ dst,
                               int B, int C, int HW, int Ctot, int coff) {
    int idx = blockIdx.x * blockDim.x + threadIdx.x;
    int total = B * C * HW;
    if (idx >= total) return;
    int p = idx % HW; int t = idx / HW;
    int c = t % C; int b = t / C;
    dst[((size_t)b * Ctot + coff + c) * HW + p] = src[idx];
}

// ------------------------- batchnorm (batch stats, in-place) ----------------
// h (4,512,32,32); one block per channel; N=4096 per channel
__global__ void bn_kernel(float* __restrict__ h, const float* __restrict__ g,
                          const float* __restrict__ be) {
    __shared__ float sred[256];
    __shared__ float s_mean, s_rstd;
    int c = blockIdx.x, tid = threadIdx.x;
    float vals[16];
    float s = 0.f;
#pragma unroll
    for (int i = 0; i < 16; i++) {
        int e = tid + i * 256;           // 0..4095
        int b = e >> 10; int p = e & 1023;
        float v = h[(((size_t)b * 512 + c) << 10) + p];
        vals[i] = v; s += v;
    }
    sred[tid] = s; __syncthreads();
    for (int st = 128; st > 0; st >>= 1) {
        if (tid < st) sred[tid] += sred[tid + st];
        __syncthreads();
    }
    if (tid == 0) s_mean = sred[0] * (1.f / 4096.f);
    __syncthreads();
    float mean = s_mean;
    float sq = 0.f;
#pragma unroll
    for (int i = 0; i < 16; i++) { float d = vals[i] - mean; sq += d * d; }
    sred[tid] = sq; __syncthreads();
    for (int st = 128; st > 0; st >>= 1) {
        if (tid < st) sred[tid] += sred[tid + st];
        __syncthreads();
    }
    if (tid == 0) s_rstd = rsqrtf(sred[0] * (1.f / 4096.f) + BN_EPS);
    __syncthreads();
    float gamma = g[c], beta = be[c], rstd = s_rstd;
#pragma unroll
    for (int i = 0; i < 16; i++) {
        int e = tid + i * 256;
        int b = e >> 10; int p = e & 1023;
        h[(((size_t)b * 512 + c) << 10) + p] = gamma * (vals[i] - mean) * rstd + beta;
    }
}

// ------------------------- final 1x1 conv -----------------------------------
__global__ void conv1x1_kernel(const float* __restrict__ in, const float* __restrict__ wl,
                               const float* __restrict__ bl, float* __restrict__ out) {
    int idx = blockIdx.x * blockDim.x + threadIdx.x;
    const int HW = 256 * 256;
    int total = 4 * HW;
    if (idx >= total) return;
    int p = idx % HW; int b = idx / HW;
    float acc = bl[0];
    const float* pb = in + (size_t)b * 32 * HW + p;
#pragma unroll
    for (int ci = 0; ci < 32; ci++)
        acc = fmaf(pb[(size_t)ci * HW], wl[ci], acc);
    out[idx] = acc;
}

// ------------------------- launch ------------------------------------------
static inline int ceildiv(int a, int b) { return (a + b - 1) / b; }

extern "C" void kernel_launch(void* const* d_in, const int* in_sizes, int n_in,
                              void* d_out, int out_size) {
    (void)in_sizes; (void)n_in; (void)out_size;
    float* buf = nullptr;
    cudaGetSymbolAddress((void**)&buf, g_buf);

    const float* x    = (const float*)d_in[0];
    const float* w    = (const float*)d_in[1];
    const float* d1w  = (const float*)d_in[2];
    const float* d1b  = (const float*)d_in[3];
    const float* w2a  = (const float*)d_in[4];
    const float* b2a  = (const float*)d_in[5];
    const float* w2b  = (const float*)d_in[6];
    const float* b2b  = (const float*)d_in[7];
    const float* w3a  = (const float*)d_in[8];
    const float* b3a  = (const float*)d_in[9];
    const float* w3b  = (const float*)d_in[10];
    const float* b3b  = (const float*)d_in[11];
    const float* w4a  = (const float*)d_in[12];
    const float* b4a  = (const float*)d_in[13];
    const float* w4b  = (const float*)d_in[14];
    const float* b4b  = (const float*)d_in[15];
    const float* g4   = (const float*)d_in[16];
    const float* be4  = (const float*)d_in[17];
    const float* u3a  = (const float*)d_in[18];
    const float* ub3a = (const float*)d_in[19];
    const float* u3b  = (const float*)d_in[20];
    const float* ub3b = (const float*)d_in[21];
    const float* u2a  = (const float*)d_in[22];
    const float* ub2a = (const float*)d_in[23];
    const float* u2b  = (const float*)d_in[24];
    const float* ub2b = (const float*)d_in[25];
    const float* u1a  = (const float*)d_in[26];
    const float* ub1a = (const float*)d_in[27];
    const float* u1b  = (const float*)d_in[28];
    const float* ub1b = (const float*)d_in[29];
    const float* wl   = (const float*)d_in[30];
    const float* bl   = (const float*)d_in[31];

    float* T0   = buf + OFF_T0;
    float* C1   = buf + OFF_C1;
    float* P1   = buf + OFF_P1;
    float* A2   = buf + OFF_A2;
    float* C2   = buf + OFF_C2;
    float* P2   = buf + OFF_P2;
    float* A3   = buf + OFF_A3;
    float* C3   = buf + OFF_C3;
    float* P3   = buf + OFF_P3;
    float* A4   = buf + OFF_A4;
    float* H4   = buf + OFF_H4;
    float* CAT3 = buf + OFF_CAT3;
    float* A5   = buf + OFF_A5;
    float* U3   = buf + OFF_U3;
    float* CAT2 = buf + OFF_CAT2;
    float* A6   = buf + OFF_A6;
    float* U2   = buf + OFF_U2;
    float* CAT1 = buf + OFF_CAT1;
    float* A7   = buf + OFF_A7;
    float* U1   = buf + OFF_U1;

    // 1. dyn conv + mish: (4,32,255,255)
    {
        int total = 4 * 32 * 255 * 255;
        dynconv_mish_kernel<<<ceildiv(total, 256), 256>>>(x, w, T0);
    }
    // 2. d1 conv 4x4 pad2 + mish -> C1 (4,32,256,256)
    conv_tiled<4, true><<<dim3(256 / TW, 256 / TH, 4 * (32 / GC)), NT>>>(
        T0, d1w, d1b, C1, 32, 255, 255, 32, 256, 256, 2);
    // 3. pool -> P1 (4,32,128,128)
    maxpool_kernel<<<ceildiv(4 * 32 * 128 * 128, 256), 256>>>(C1, P1, 4 * 32, 256, 256);
    // 4-5. block2
    conv_tiled<3, true><<<dim3(128 / TW, 128 / TH, 4 * (128 / GC)), NT>>>(
        P1, w2a, b2a, A2, 32, 128, 128, 128, 128, 128, 1);
    conv_tiled<3, true><<<dim3(128 / TW, 128 / TH, 4 * (128 / GC)), NT>>>(
        A2, w2b, b2b, C2, 128, 128, 128, 128, 128, 128, 1);
    // 6. pool -> P2
    maxpool_kernel<<<ceildiv(4 * 128 * 64 * 64, 256), 256>>>(C2, P2, 4 * 128, 128, 128);
    // 7-8. block3
    conv_tiled<3, true><<<dim3(64 / TW, 64 / TH, 4 * (256 / GC)), NT>>>(
        P2, w3a, b3a, A3, 128, 64, 64, 256, 64, 64, 1);
    conv_tiled<3, true><<<dim3(64 / TW, 64 / TH, 4 * (256 / GC)), NT>>>(
        A3, w3b, b3b, C3, 256, 64, 64, 256, 64, 64, 1);
    // 9. pool -> P3
    maxpool_kernel<<<ceildiv(4 * 256 * 32 * 32, 256), 256>>>(C3, P3, 4 * 256, 64, 64);
    // 10-11. block4
    conv_tiled<3, true><<<dim3(32 / TW, 32 / TH, 4 * (512 / GC)), NT>>>(
        P3, w4a, b4a, A4, 256, 32, 32, 512, 32, 32, 1);
    conv_tiled<3, true><<<dim3(32 / TW, 32 / TH, 4 * (512 / GC)), NT>>>(
        A4, w4b, b4b, H4, 512, 32, 32, 512, 32, 32, 1);
    // 12. batchnorm in-place
    bn_kernel<<<512, 256>>>(H4, g4, be4);
    // 13-14. up + concat c3 -> CAT3 (4,768,64,64)
    up2_kernel<<<ceildiv(4 * 512 * 64 * 64, 256), 256>>>(
        H4, CAT3, 4, 512, 32, 32, 768, 0, 31.f / 63.f);
    catcopy_kernel<<<ceildiv(4 * 256 * 64 * 64, 256), 256>>>(
        C3, CAT3, 4, 256, 64 * 64, 768, 512);
    // 15-16. up-block3
    conv_tiled<3, true><<<dim3(64 / TW, 64 / TH, 4 * (256 / GC)), NT>>>(
        CAT3, u3a, ub3a, A5, 768, 64, 64, 256, 64, 64, 1);
    conv_tiled<3, true><<<dim3(64 / TW, 64 / TH, 4 * (256 / GC)), NT>>>(
        A5, u3b, ub3b, U3, 256, 64, 64, 256, 64, 64, 1);
    // 17-18. up + concat c2 -> CAT2 (4,384,128,128)
    up2_kernel<<<ceildiv(4 * 256 * 128 * 128, 256), 256>>>(
        U3, CAT2, 4, 256, 64, 64, 384, 0, 63.f / 127.f);
    catcopy_kernel<<<ceildiv(4 * 128 * 128 * 128, 256), 256>>>(
        C2, CAT2, 4, 128, 128 * 128, 384, 256);
    // 19-20. up-block2
    conv_tiled<3, true><<<dim3(128 / TW, 128 / TH, 4 * (128 / GC)), NT>>>(
        CAT2, u2a, ub2a, A6, 384, 128, 128, 128, 128, 128, 1);
    conv_tiled<3, true><<<dim3(128 / TW, 128 / TH, 4 * (128 / GC)), NT>>>(
        A6, u2b, ub2b, U2, 128, 128, 128, 128, 128, 128, 1);
    // 21-22. up + concat c1 -> CAT1 (4,160,256,256)
    up2_kernel<<<ceildiv(4 * 128 * 256 * 256, 256), 256>>>(
        U2, CAT1, 4, 128, 128, 128, 160, 0, 127.f / 255.f);
    catcopy_kernel<<<ceildiv(4 * 32 * 256 * 256, 256), 256>>>(
        C1, CAT1, 4, 32, 256 * 256, 160, 128);
    // 23-24. up-block1
    conv_tiled<3, true><<<dim3(256 / TW, 256 / TH, 4 * (32 / GC)), NT>>>(
        CAT1, u1a, ub1a, A7, 160, 256, 256, 32, 256, 256, 1);
    conv_tiled<3, true><<<dim3(256 / TW, 256 / TH, 4 * (32 / GC)), NT>>>(
        A7, u1b, ub1b, U1, 32, 256, 256, 32, 256, 256, 1);
    // 25. final 1x1
    conv1x1_kernel<<<ceildiv(4 * 256 * 256, 256), 256>>>(U1, wl, bl, (float*)d_out);
}

// round 8
// speedup vs baseline: 1.1318x; 1.1318x over previous
#include <cuda_runtime.h>
#include <cuda_bf16.h>
#include <math.h>

// ---------------------------------------------------------------------------
// UNet forward, fp32 with packed f32x2 FMA conv kernels.
// Inputs (metadata order):
//  0 x(4,1,256,256) 1 w(4,32,4,4) 2 d1w(32,32,4,4) 3 d1b(32)
//  4 w2a(128,32,3,3) 5 b2a 6 w2b(128,128,3,3) 7 b2b
//  8 w3a(256,128,3,3) 9 b3a 10 w3b(256,256,3,3) 11 b3b
// 12 w4a(512,256,3,3) 13 b4a 14 w4b(512,512,3,3) 15 b4b
// 16 g4(512) 17 be4(512)
// 18 u3a(256,768,3,3) 19 ub3a 20 u3b(256,256,3,3) 21 ub3b
// 22 u2a(128,384,3,3) 23 ub2a 24 u2b(128,128,3,3) 25 ub2b
// 26 u1a(32,160,3,3) 27 ub1a 28 u1b(32,32,3,3) 29 ub1b
// 30 wl(1,32,1,1) 31 bl(1)
// ---------------------------------------------------------------------------

#define BN_EPS 1e-5f
typedef unsigned long long ull;

// ------------------------- scratch buffers ---------------------------------
constexpr size_t SZ_T0   = 4ul*32*255*255;
constexpr size_t SZ_C1   = 4ul*32*256*256;
constexpr size_t SZ_P1   = 4ul*32*128*128;
constexpr size_t SZ_A2   = 4ul*128*128*128;
constexpr size_t SZ_C2   = 4ul*128*128*128;
constexpr size_t SZ_P2   = 4ul*128*64*64;
constexpr size_t SZ_A3   = 4ul*256*64*64;
constexpr size_t SZ_C3   = 4ul*256*64*64;
constexpr size_t SZ_P3   = 4ul*256*32*32;
constexpr size_t SZ_A4   = 4ul*512*32*32;
constexpr size_t SZ_H4   = 4ul*512*32*32;
constexpr size_t SZ_CAT3 = 4ul*768*64*64;
constexpr size_t SZ_A5   = 4ul*256*64*64;
constexpr size_t SZ_U3   = 4ul*256*64*64;
constexpr size_t SZ_CAT2 = 4ul*384*128*128;
constexpr size_t SZ_A6   = 4ul*128*128*128;
constexpr size_t SZ_U2   = 4ul*128*128*128;
constexpr size_t SZ_CAT1 = 4ul*160*256*256;
constexpr size_t SZ_A7   = 4ul*32*256*256;
constexpr size_t SZ_U1   = 4ul*32*256*256;

constexpr size_t OFF_T0   = 0;
constexpr size_t OFF_C1   = OFF_T0   + SZ_T0;
constexpr size_t OFF_P1   = OFF_C1   + SZ_C1;
constexpr size_t OFF_A2   = OFF_P1   + SZ_P1;
constexpr size_t OFF_C2   = OFF_A2   + SZ_A2;
constexpr size_t OFF_P2   = OFF_C2   + SZ_C2;
constexpr size_t OFF_A3   = OFF_P2   + SZ_P2;
constexpr size_t OFF_C3   = OFF_A3   + SZ_A3;
constexpr size_t OFF_P3   = OFF_C3   + SZ_C3;
constexpr size_t OFF_A4   = OFF_P3   + SZ_P3;
constexpr size_t OFF_H4   = OFF_A4   + SZ_A4;
constexpr size_t OFF_CAT3 = OFF_H4   + SZ_H4;
constexpr size_t OFF_A5   = OFF_CAT3 + SZ_CAT3;
constexpr size_t OFF_U3   = OFF_A5   + SZ_A5;
constexpr size_t OFF_CAT2 = OFF_U3   + SZ_U3;
constexpr size_t OFF_A6   = OFF_CAT2 + SZ_CAT2;
constexpr size_t OFF_U2   = OFF_A6   + SZ_A6;
constexpr size_t OFF_CAT1 = OFF_U2   + SZ_U2;
constexpr size_t OFF_A7   = OFF_CAT1 + SZ_CAT1;
constexpr size_t OFF_U1   = OFF_A7   + SZ_A7;
constexpr size_t TOTAL_F  = OFF_U1   + SZ_U1;

__device__ float g_buf[TOTAL_F];

// ------------------------- f32x2 helpers ------------------------------------
__device__ __forceinline__ void fma2(ull& d, ull a, ull b) {
    asm("fma.rn.f32x2 %0, %1, %2, %3;" : "=l"(d) : "l"(a), "l"(b), "l"(d));
}
__device__ __forceinline__ ull pack2(float lo, float hi) {
    ull r; asm("mov.b64 %0, {%1, %2};" : "=l"(r) : "f"(lo), "f"(hi)); return r;
}
__device__ __forceinline__ void unpack2(ull v, float& lo, float& hi) {
    asm("mov.b64 {%0, %1}, %2;" : "=f"(lo), "=f"(hi) : "l"(v));
}

// ------------------------- helpers -----------------------------------------
__device__ __forceinline__ float mishf(float x) {
    // mish(x) = x * tanh(softplus(x)) = x * u/(u+2), u = e^x (e^x + 2)  (exact)
    if (x > 8.5f) return x;
    float t = __expf(x);
    float u = t * (t + 2.f);
    return x * __fdividef(u, u + 2.f);
}

// ------------------------- dyn conv + mish ----------------------------------
__global__ void dynconv_mish_kernel(const float* __restrict__ x,
                                    const float* __restrict__ w,
                                    float* __restrict__ out) {
    const int HO = 255, WO = 255;
    int idx = blockIdx.x * blockDim.x + threadIdx.x;
    int total = 4 * 32 * HO * WO;
    if (idx >= total) return;
    int ox = idx % WO; int t = idx / WO;
    int oy = t % HO;  t /= HO;
    int co = t & 31;  int b = t >> 5;
    const float* xb = x + (size_t)b * 256 * 256;
    const float* wb = w + ((size_t)(b * 32 + co) << 4);
    float acc = 0.f;
#pragma unroll
    for (int ky = 0; ky < 4; ky++) {
        int iy = oy - 1 + ky;
        if (iy < 0 || iy >= 256) continue;
#pragma unroll
        for (int kx = 0; kx < 4; kx++) {
            int ix = ox - 1 + kx;
            if (ix < 0 || ix >= 256) continue;
            acc = fmaf(xb[iy * 256 + ix], wb[ky * 4 + kx], acc);
        }
    }
    out[idx] = mishf(acc);
}

// ------------------------- tiled conv, f32x2 --------------------------------
// Output tile 32x32, 128 threads: tx=tid&3 (8-px group), ty=tid>>2 (row).
// 8 out-channels/block, 8 in-channels/chunk. f32x2 packed FMA.
// Requires: Wo%32==0, Ho%32==0, Co%8==0, Ci%8==0.
constexpr int CGC = 8;   // out channels per block
constexpr int CCC = 8;   // in channels per chunk

template<int K>
__global__ __launch_bounds__(128) void conv_f2(
    const float* __restrict__ in, const float* __restrict__ wgt,
    const float* __restrict__ bias, float* __restrict__ out,
    int Ci, int Hi, int Wi, int Co, int Ho, int Wo, int pad)
{
    constexpr int SH = 32 + K - 1;      // 34 / 35
    constexpr int SW = 32 + K - 1;
    constexpr int SWP = 36;             // padded row (floats), 144B
    constexpr int WROW = 8;             // floats per ky row (dup pairs)
    constexpr int WSZ = K * WROW;       // floats per (cc,g)
    __shared__ __align__(16) float s_tile[CCC][SH][SWP];
    __shared__ __align__(16) float s_w[CCC * CGC][WSZ];

    const int tid = threadIdx.x;
    const int tx = tid & 3;
    const int ty = tid >> 2;
    const int ox0 = blockIdx.x * 32;
    const int oy0 = blockIdx.y * 32;
    const int ngrp = Co >> 3;
    const int b = blockIdx.z / ngrp;
    const int co0 = (blockIdx.z - b * ngrp) << 3;
    const int KK = K * K;

    ull acc[CGC][4];
#pragma unroll
    for (int g = 0; g < CGC; g++)
#pragma unroll
        for (int j = 0; j < 4; j++) acc[g][j] = 0ull;

    const size_t plane = (size_t)Hi * Wi;
    const float* inb = in + (size_t)b * Ci * plane;

    for (int ci0 = 0; ci0 < Ci; ci0 += CCC) {
        __syncthreads();
        // ---- load input tile (8 channels) ----
#pragma unroll 1
        for (int cc = 0; cc < CCC; cc++) {
            const float* chp = inb + (size_t)(ci0 + cc) * plane;
            for (int idx = tid; idx < SH * SW; idx += 128) {
                int sy = idx / SW;
                int sx = idx - sy * SW;
                int iy = oy0 - pad + sy;
                int ix = ox0 - pad + sx;
                float v = 0.f;
                if ((unsigned)iy < (unsigned)Hi && (unsigned)ix < (unsigned)Wi)
                    v = __ldg(chp + (size_t)iy * Wi + ix);
                s_tile[cc][sy][sx] = v;
            }
        }
        // ---- load weights, duplicated pairs ----
        for (int idx = tid; idx < CCC * CGC * KK; idx += 128) {
            int cc = idx / (CGC * KK);
            int r = idx - cc * (CGC * KK);
            int g = r / KK;
            int t = r - g * KK;
            int ky = t / K, kx = t - ky * K;
            float v = wgt[((size_t)(co0 + g) * Ci + ci0 + cc) * KK + t];
            float* p = &s_w[cc * CGC + g][ky * WROW + kx * 2];
            p[0] = v; p[1] = v;
        }
        __syncthreads();

        const float* tbase0 = &s_tile[0][ty][tx * 8];
#pragma unroll 1
        for (int cc = 0; cc < CCC; cc++) {
            const float* tb = tbase0 + cc * (SH * SWP);
            const float* wb = &s_w[cc * CGC][0];
#pragma unroll
            for (int ky = 0; ky < K; ky++) {
                const float4* rp = (const float4*)(tb + ky * SWP);
                float4 q0 = rp[0], q1 = rp[1], q2 = rp[2];
                ull e0 = pack2(q0.x, q0.y), e1 = pack2(q0.z, q0.w);
                ull e2 = pack2(q1.x, q1.y), e3 = pack2(q1.z, q1.w);
                ull e4 = pack2(q2.x, q2.y);
                ull o0 = pack2(q0.y, q0.z), o1 = pack2(q0.w, q1.x);
                ull o2 = pack2(q1.y, q1.z), o3 = pack2(q1.w, q2.x);
                ull o4 = 0ull;
                if (K == 4) o4 = pack2(q2.y, q2.z);
#pragma unroll
                for (int g = 0; g < CGC; g++) {
                    const ull* wr = (const ull*)(wb + g * WSZ + ky * WROW);
                    ull w0 = wr[0], w1 = wr[1], w2 = wr[2];
                    fma2(acc[g][0], e0, w0); fma2(acc[g][1], e1, w0);
                    fma2(acc[g][2], e2, w0); fma2(acc[g][3], e3, w0);
                    fma2(acc[g][0], o0, w1); fma2(acc[g][1], o1, w1);
                    fma2(acc[g][2], o2, w1); fma2(acc[g][3], o3, w1);
                    fma2(acc[g][0], e1, w2); fma2(acc[g][1], e2, w2);
                    fma2(acc[g][2], e3, w2); fma2(acc[g][3], e4, w2);
                    if (K == 4) {
                        ull w3 = wr[3];
                        fma2(acc[g][0], o1, w3); fma2(acc[g][1], o2, w3);
                        fma2(acc[g][2], o3, w3); fma2(acc[g][3], o4, w3);
                    }
                }
            }
        }
    }

    // ---- epilogue: bias + mish + store ----
    const int oy = oy0 + ty;
    const int ox = ox0 + tx * 8;
#pragma unroll
    for (int g = 0; g < CGC; g++) {
        float bv = bias[co0 + g];
        float v[8];
#pragma unroll
        for (int j = 0; j < 4; j++) unpack2(acc[g][j], v[2 * j], v[2 * j + 1]);
#pragma unroll
        for (int p = 0; p < 8; p++) v[p] = mishf(v[p] + bv);
        float4* op = (float4*)(out + (((size_t)b * Co + co0 + g) * Ho + oy) * Wo + ox);
        op[0] = make_float4(v[0], v[1], v[2], v[3]);
        op[1] = make_float4(v[4], v[5], v[6], v[7]);
    }
}

// ------------------------- maxpool 2x2 --------------------------------------
__global__ void maxpool_kernel(const float* __restrict__ in, float* __restrict__ out,
                               int BC, int Hi, int Wi) {
    int Ho = Hi >> 1, Wo = Wi >> 1;
    int idx = blockIdx.x * blockDim.x + threadIdx.x;
    int total = BC * Ho * Wo;
    if (idx >= total) return;
    int ox = idx % Wo; int t = idx / Wo;
    int oy = t % Ho; int bc = t / Ho;
    const float* p = in + ((size_t)bc * Hi + 2 * oy) * Wi + 2 * ox;
    float m = fmaxf(fmaxf(p[0], p[1]), fmaxf(p[Wi], p[Wi + 1]));
    out[idx] = m;
}

// ------------------------- bilinear up x2 (align_corners) -------------------
__global__ void up2_kernel(const float* __restrict__ in, float* __restrict__ out,
                           int B, int C, int H, int W, int Ctot, int coff, float scale) {
    int Ho = 2 * H, Wo = 2 * W;
    int idx = blockIdx.x * blockDim.x + threadIdx.x;
    int total = B * C * Ho * Wo;
    if (idx >= total) return;
    int ox = idx % Wo; int t = idx / Wo;
    int oy = t % Ho; t /= Ho;
    int c = t % C; int b = t / C;
    float sy = oy * scale;
    float sx = ox * scale;
    int y0 = (int)floorf(sy); int y1 = min(y0 + 1, H - 1); float fy = sy - y0;
    int x0 = (int)floorf(sx); int x1 = min(x0 + 1, W - 1); float fx = sx - x0;
    const float* p = in + ((size_t)b * C + c) * H * W;
    float v00 = p[y0 * W + x0], v01 = p[y0 * W + x1];
    float v10 = p[y1 * W + x0], v11 = p[y1 * W + x1];
    float a0 = v00 * (1.f - fy) + v10 * fy;
    float a1 = v01 * (1.f - fy) + v11 * fy;
    out[((size_t)b * Ctot + coff + c) * Ho * Wo + (size_t)oy * Wo + ox] =
        a0 * (1.f - fx) + a1 * fx;
}

// ------------------------- skip copy into concat ----------------------------
__global__ void catcopy_kernel(const float* __restrict__ src, float* __restrict__ dst,
                               int B, int C, int HW, int Ctot, int coff) {
    int idx = blockIdx.x * blockDim.x + threadIdx.x;
    int total = B * C * HW;
    if (idx >= total) return;
    int p = idx % HW; int t = idx / HW;
    int c = t % C; int b = t / C;
    dst[((size_t)b * Ctot + coff + c) * HW + p] = src[idx];
}

// ------------------------- batchnorm ----------------------------------------
__global__ void bn_kernel(float* __restrict__ h, const float* __restrict__ g,
                          const float* __restrict__ be) {
    __shared__ float sred[256];
    __shared__ float s_mean, s_rstd;
    int c = blockIdx.x, tid = threadIdx.x;
    float vals[16];
    float s = 0.f;
#pragma unroll
    for (int i = 0; i < 16; i++) {
        int e = tid + i * 256;
        int b = e >> 10; int p = e & 1023;
        float v = h[(((size_t)b * 512 + c) << 10) + p];
        vals[i] = v; s += v;
    }
    sred[tid] = s; __syncthreads();
    for (int st = 128; st > 0; st >>= 1) {
        if (tid < st) sred[tid] += sred[tid + st];
        __syncthreads();
    }
    if (tid == 0) s_mean = sred[0] * (1.f / 4096.f);
    __syncthreads();
    float mean = s_mean;
    float sq = 0.f;
#pragma unroll
    for (int i = 0; i < 16; i++) { float d = vals[i] - mean; sq += d * d; }
    sred[tid] = sq; __syncthreads();
    for (int st = 128; st > 0; st >>= 1) {
        if (tid < st) sred[tid] += sred[tid + st];
        __syncthreads();
    }
    if (tid == 0) s_rstd = rsqrtf(sred[0] * (1.f / 4096.f) + BN_EPS);
    __syncthreads();
    float gamma = g[c], beta = be[c], rstd = s_rstd;
#pragma unroll
    for (int i = 0; i < 16; i++) {
        int e = tid + i * 256;
        int b = e >> 10; int p = e & 1023;
        h[(((size_t)b * 512 + c) << 10) + p] = gamma * (vals[i] - mean) * rstd + beta;
    }
}

// ------------------------- final 1x1 conv -----------------------------------
__global__ void conv1x1_kernel(const float* __restrict__ in, const float* __restrict__ wl,
                               const float* __restrict__ bl, float* __restrict__ out) {
    int idx = blockIdx.x * blockDim.x + threadIdx.x;
    const int HW = 256 * 256;
    int total = 4 * HW;
    if (idx >= total) return;
    int p = idx % HW; int b = idx / HW;
    float acc = bl[0];
    const float* pb = in + (size_t)b * 32 * HW + p;
#pragma unroll
    for (int ci = 0; ci < 32; ci++)
        acc = fmaf(pb[(size_t)ci * HW], wl[ci], acc);
    out[idx] = acc;
}

// ------------------------- launch ------------------------------------------
static inline int ceildiv(int a, int b) { return (a + b - 1) / b; }

extern "C" void kernel_launch(void* const* d_in, const int* in_sizes, int n_in,
                              void* d_out, int out_size) {
    (void)in_sizes; (void)n_in; (void)out_size;
    float* buf = nullptr;
    cudaGetSymbolAddress((void**)&buf, g_buf);

    const float* x    = (const float*)d_in[0];
    const float* w    = (const float*)d_in[1];
    const float* d1w  = (const float*)d_in[2];
    const float* d1b  = (const float*)d_in[3];
    const float* w2a  = (const float*)d_in[4];
    const float* b2a  = (const float*)d_in[5];
    const float* w2b  = (const float*)d_in[6];
    const float* b2b  = (const float*)d_in[7];
    const float* w3a  = (const float*)d_in[8];
    const float* b3a  = (const float*)d_in[9];
    const float* w3b  = (const float*)d_in[10];
    const float* b3b  = (const float*)d_in[11];
    const float* w4a  = (const float*)d_in[12];
    const float* b4a  = (const float*)d_in[13];
    const float* w4b  = (const float*)d_in[14];
    const float* b4b  = (const float*)d_in[15];
    const float* g4   = (const float*)d_in[16];
    const float* be4  = (const float*)d_in[17];
    const float* u3a  = (const float*)d_in[18];
    const float* ub3a = (const float*)d_in[19];
    const float* u3b  = (const float*)d_in[20];
    const float* ub3b = (const float*)d_in[21];
    const float* u2a  = (const float*)d_in[22];
    const float* ub2a = (const float*)d_in[23];
    const float* u2b  = (const float*)d_in[24];
    const float* ub2b = (const float*)d_in[25];
    const float* u1a  = (const float*)d_in[26];
    const float* ub1a = (const float*)d_in[27];
    const float* u1b  = (const float*)d_in[28];
    const float* ub1b = (const float*)d_in[29];
    const float* wl   = (const float*)d_in[30];
    const float* bl   = (const float*)d_in[31];

    float* T0   = buf + OFF_T0;
    float* C1   = buf + OFF_C1;
    float* P1   = buf + OFF_P1;
    float* A2   = buf + OFF_A2;
    float* C2   = buf + OFF_C2;
    float* P2   = buf + OFF_P2;
    float* A3   = buf + OFF_A3;
    float* C3   = buf + OFF_C3;
    float* P3   = buf + OFF_P3;
    float* A4   = buf + OFF_A4;
    float* H4   = buf + OFF_H4;
    float* CAT3 = buf + OFF_CAT3;
    float* A5   = buf + OFF_A5;
    float* U3   = buf + OFF_U3;
    float* CAT2 = buf + OFF_CAT2;
    float* A6   = buf + OFF_A6;
    float* U2   = buf + OFF_U2;
    float* CAT1 = buf + OFF_CAT1;
    float* A7   = buf + OFF_A7;
    float* U1   = buf + OFF_U1;

    // 1. dyn conv + mish
    {
        int total = 4 * 32 * 255 * 255;
        dynconv_mish_kernel<<<ceildiv(total, 256), 256>>>(x, w, T0);
    }
    // 2. d1 conv 4x4 pad2 + mish -> C1 (4,32,256,256)
    conv_f2<4><<<dim3(8, 8, 4 * (32 / CGC)), 128>>>(
        T0, d1w, d1b, C1, 32, 255, 255, 32, 256, 256, 2);
    // 3. pool
    maxpool_kernel<<<ceildiv(4 * 32 * 128 * 128, 256), 256>>>(C1, P1, 4 * 32, 256, 256);
    // 4-5. block2 (128x128)
    conv_f2<3><<<dim3(4, 4, 4 * (128 / CGC)), 128>>>(
        P1, w2a, b2a, A2, 32, 128, 128, 128, 128, 128, 1);
    conv_f2<3><<<dim3(4, 4, 4 * (128 / CGC)), 128>>>(
        A2, w2b, b2b, C2, 128, 128, 128, 128, 128, 128, 1);
    // 6. pool
    maxpool_kernel<<<ceildiv(4 * 128 * 64 * 64, 256), 256>>>(C2, P2, 4 * 128, 128, 128);
    // 7-8. block3 (64x64)
    conv_f2<3><<<dim3(2, 2, 4 * (256 / CGC)), 128>>>(
        P2, w3a, b3a, A3, 128, 64, 64, 256, 64, 64, 1);
    conv_f2<3><<<dim3(2, 2, 4 * (256 / CGC)), 128>>>(
        A3, w3b, b3b, C3, 256, 64, 64, 256, 64, 64, 1);
    // 9. pool
    maxpool_kernel<<<ceildiv(4 * 256 * 32 * 32, 256), 256>>>(C3, P3, 4 * 256, 64, 64);
    // 10-11. block4 (32x32)
    conv_f2<3><<<dim3(1, 1, 4 * (512 / CGC)), 128>>>(
        P3, w4a, b4a, A4, 256, 32, 32, 512, 32, 32, 1);
    conv_f2<3><<<dim3(1, 1, 4 * (512 / CGC)), 128>>>(
        A4, w4b, b4b, H4, 512, 32, 32, 512, 32, 32, 1);
    // 12. batchnorm
    bn_kernel<<<512, 256>>>(H4, g4, be4);
    // 13-14. up + concat c3
    up2_kernel<<<ceildiv(4 * 512 * 64 * 64, 256), 256>>>(
        H4, CAT3, 4, 512, 32, 32, 768, 0, 31.f / 63.f);
    catcopy_kernel<<<ceildiv(4 * 256 * 64 * 64, 256), 256>>>(
        C3, CAT3, 4, 256, 64 * 64, 768, 512);
    // 15-16. up-block3 (64x64)
    conv_f2<3><<<dim3(2, 2, 4 * (256 / CGC)), 128>>>(
        CAT3, u3a, ub3a, A5, 768, 64, 64, 256, 64, 64, 1);
    conv_f2<3><<<dim3(2, 2, 4 * (256 / CGC)), 128>>>(
        A5, u3b, ub3b, U3, 256, 64, 64, 256, 64, 64, 1);
    // 17-18. up + concat c2
    up2_kernel<<<ceildiv(4 * 256 * 128 * 128, 256), 256>>>(
        U3, CAT2, 4, 256, 64, 64, 384, 0, 63.f / 127.f);
    catcopy_kernel<<<ceildiv(4 * 128 * 128 * 128, 256), 256>>>(
        C2, CAT2, 4, 128, 128 * 128, 384, 256);
    // 19-20. up-block2 (128x128)
    conv_f2<3><<<dim3(4, 4, 4 * (128 / CGC)), 128>>>(
        CAT2, u2a, ub2a, A6, 384, 128, 128, 128, 128, 128, 1);
    conv_f2<3><<<dim3(4, 4, 4 * (128 / CGC)), 128>>>(
        A6, u2b, ub2b, U2, 128, 128, 128, 128, 128, 128, 1);
    // 21-22. up + concat c1
    up2_kernel<<<ceildiv(4 * 128 * 256 * 256, 256), 256>>>(
        U2, CAT1, 4, 128, 128, 128, 160, 0, 127.f / 255.f);
    catcopy_kernel<<<ceildiv(4 * 32 * 256 * 256, 256), 256>>>(
        C1, CAT1, 4, 32, 256 * 256, 160, 128);
    // 23-24. up-block1 (256x256)
    conv_f2<3><<<dim3(8, 8, 4 * (32 / CGC)), 128>>>(
        CAT1, u1a, ub1a, A7, 160, 256, 256, 32, 256, 256, 1);
    conv_f2<3><<<dim3(8, 8, 4 * (32 / CGC)), 128>>>(
        A7, u1b, ub1b, U1, 32, 256, 256, 32, 256, 256, 1);
    // 25. final 1x1
    conv1x1_kernel<<<ceildiv(4 * 256 * 256, 256), 256>>>(U1, wl, bl, (float*)d_out);
}